// round 14
// baseline (speedup 1.0000x reference)
#include <cuda_runtime.h>
#include <cstdint>

#define NB 4
#define NH 16
#define LSEQ 2048
#define HDIM 64
#define DMODEL 1024
#define M_TOT (NB*LSEQ)            // 8192
#define OUT_ELEMS (M_TOT*DMODEL)   // 8388608
#define SQS (64*68)

// GEMM v4 tiling: BM=128, BN=128, BK=32, 128 threads, 8x16/thread, double-buffered
#define GBK 32
#define GNCHUNK (DMODEL/GBK)       // 32
#define G_TILE_F (GBK*132)         // floats per (A or B) buffer: 4224
#define G_SMEM_B (4*G_TILE_F*4)    // 2 bufs x (A+B) = 67584 bytes

// flash4: Q-block 128 rows, 128 threads, 8x8/thread
#define FSHM ((128+64+64+128)*68*4)   // Qs,Kt,Vs,Ps = 104448 bytes

typedef unsigned long long u64;

// ---- packed fp32x2 helpers ----
__device__ __forceinline__ u64 pk2(float lo, float hi) {
    u64 r; asm("mov.b64 %0, {%1, %2};" : "=l"(r) : "f"(lo), "f"(hi)); return r;
}
__device__ __forceinline__ void upk2(u64 v, float& lo, float& hi) {
    asm("mov.b64 {%0, %1}, %2;" : "=f"(lo), "=f"(hi) : "l"(v));
}
__device__ __forceinline__ void fma2(u64& d, u64 a, u64 b) {
    asm("fma.rn.f32x2 %0, %1, %2, %3;" : "=l"(d) : "l"(a), "l"(b), "l"(d));
}
__device__ __forceinline__ void mul2(u64& d, u64 a, u64 b) {
    asm("mul.rn.f32x2 %0, %1, %2;" : "=l"(d) : "l"(a), "l"(b));
}

// Scratch (device globals; no allocation allowed)
__device__ float g_q[NB*NH*LSEQ*HDIM];
__device__ float g_k[NB*NH*LSEQ*HDIM];
__device__ float g_v[NB*NH*LSEQ*HDIM];
__device__ float g_o[NB*NH*LSEQ*HDIM];
__device__ float g_m[NB*NH*LSEQ];
__device__ float g_s[NB*NH*LSEQ];

// ===========================================================================
// GEMM core (packed f32x2, 0.75 B/MAC): C[m,n] = sum_k A[m,k]*W[n,k] (+bias)
// 128x128 tile, BK=32, 128 threads; per thread 8 rows x 16 cols
// (col quads at tx*4 + {0,32,64,96} -> conflict-free octet LDS).
// ===========================================================================
__device__ __forceinline__ void gemm_core(
    const float* __restrict__ A, const float* __restrict__ W,
    const float* __restrict__ bias, float* __restrict__ C,
    int gatherA, int scatterC, int bx, int by, float* gsm)
{
    const int tid = threadIdx.x;
    const int tx = tid & 7;          // col group: cols tx*4 + g*32
    const int ty = tid >> 3;         // row group: rows ty*8..+7
    const int m0 = by * 128;
    const int n0 = bx * 128;

    u64 acc2[8][8];
#pragma unroll
    for (int i = 0; i < 8; i++)
#pragma unroll
        for (int j = 0; j < 8; j++) acc2[i][j] = 0ull;

    float4 ra[8], rb[8];
#pragma unroll
    for (int ii = 0; ii < 8; ii++) {
        int idx = tid + ii * 128;
        int r = idx >> 3;
        int c4 = (idx & 7) << 2;
        if (!gatherA) {
            ra[ii] = *(const float4*)(A + (size_t)(m0 + r) * DMODEL + c4);
        } else {
            int m = m0 + r, k = c4;
            ra[ii] = *(const float4*)(A +
                (((size_t)((m >> 11) * NH + (k >> 6)) * LSEQ + (m & 2047)) * HDIM) + (k & 63));
        }
        rb[ii] = *(const float4*)(W + (size_t)(n0 + r) * DMODEL + c4);
    }

    for (int c = 0; c < GNCHUNK; c++) {
        const int buf = c & 1;
        float* As = gsm + buf * G_TILE_F;
        float* Bs = gsm + 2 * G_TILE_F + buf * G_TILE_F;

#pragma unroll
        for (int ii = 0; ii < 8; ii++) {
            int idx = tid + ii * 128;
            int r = idx >> 3;
            int c4 = (idx & 7) << 2;
            As[(c4 + 0) * 132 + r] = ra[ii].x;
            As[(c4 + 1) * 132 + r] = ra[ii].y;
            As[(c4 + 2) * 132 + r] = ra[ii].z;
            As[(c4 + 3) * 132 + r] = ra[ii].w;
            Bs[(c4 + 0) * 132 + r] = rb[ii].x;
            Bs[(c4 + 1) * 132 + r] = rb[ii].y;
            Bs[(c4 + 2) * 132 + r] = rb[ii].z;
            Bs[(c4 + 3) * 132 + r] = rb[ii].w;
        }
        __syncthreads();

        if (c + 1 < GNCHUNK) {
            int k0 = (c + 1) * GBK;
#pragma unroll
            for (int ii = 0; ii < 8; ii++) {
                int idx = tid + ii * 128;
                int r = idx >> 3;
                int c4 = (idx & 7) << 2;
                if (!gatherA) {
                    ra[ii] = *(const float4*)(A + (size_t)(m0 + r) * DMODEL + k0 + c4);
                } else {
                    int m = m0 + r, k = k0 + c4;
                    ra[ii] = *(const float4*)(A +
                        (((size_t)((m >> 11) * NH + (k >> 6)) * LSEQ + (m & 2047)) * HDIM) + (k & 63));
                }
                rb[ii] = *(const float4*)(W + (size_t)(n0 + r) * DMODEL + k0 + c4);
            }
        }

#pragma unroll
        for (int k = 0; k < GBK; k++) {
            float4 a0 = *(const float4*)&As[k * 132 + ty * 8];
            float4 a1 = *(const float4*)&As[k * 132 + ty * 8 + 4];
            u64 bp[8];
#pragma unroll
            for (int gq = 0; gq < 4; gq++) {
                float4 b = *(const float4*)&Bs[k * 132 + tx * 4 + gq * 32];
                bp[gq * 2 + 0] = pk2(b.x, b.y);
                bp[gq * 2 + 1] = pk2(b.z, b.w);
            }
            float av[8] = {a0.x, a0.y, a0.z, a0.w, a1.x, a1.y, a1.z, a1.w};
#pragma unroll
            for (int i = 0; i < 8; i++) {
                u64 ap = pk2(av[i], av[i]);
#pragma unroll
                for (int j = 0; j < 8; j++) fma2(acc2[i][j], ap, bp[j]);
            }
        }
        __syncthreads();
    }

#pragma unroll
    for (int i = 0; i < 8; i++) {
        int m = m0 + ty * 8 + i;
#pragma unroll
        for (int gq = 0; gq < 4; gq++) {
            int n = n0 + tx * 4 + gq * 32;
            float f0, f1, f2, f3;
            upk2(acc2[i][gq * 2 + 0], f0, f1);
            upk2(acc2[i][gq * 2 + 1], f2, f3);
            if (bias) {
                float4 bv = *(const float4*)(bias + n);
                f0 += bv.x; f1 += bv.y; f2 += bv.z; f3 += bv.w;
            }
            float4 o = make_float4(f0, f1, f2, f3);
            float* dst;
            if (scatterC) {
                dst = C + (((size_t)((m >> 11) * NH + (n >> 6)) * LSEQ + (m & 2047)) * HDIM)
                        + (n & 63);
            } else {
                dst = C + (size_t)m * DMODEL + n;
            }
            *(float4*)dst = o;
        }
    }
}

// Fused Q/K/V projection: blockIdx.z selects (input, weight, output).
__global__ __launch_bounds__(128) void gemm_qkv(
    const float* __restrict__ Aq, const float* __restrict__ Ak,
    const float* __restrict__ Av,
    const float* __restrict__ Wq, const float* __restrict__ Wk,
    const float* __restrict__ Wv,
    float* __restrict__ Cq, float* __restrict__ Ck, float* __restrict__ Cv)
{
    extern __shared__ float gsm[];
    const float* A; const float* W; float* C;
    if (blockIdx.z == 0)      { A = Aq; W = Wq; C = Cq; }
    else if (blockIdx.z == 1) { A = Ak; W = Wk; C = Ck; }
    else                      { A = Av; W = Wv; C = Cv; }
    gemm_core(A, W, nullptr, C, 0, 1, blockIdx.x, blockIdx.y, gsm);
}

// Output projection (head-split gather + bias).
__global__ __launch_bounds__(128) void gemm_out(
    const float* __restrict__ A, const float* __restrict__ W,
    const float* __restrict__ bias, float* __restrict__ C)
{
    extern __shared__ float gsm[];
    gemm_core(A, W, bias, C, 1, 0, blockIdx.x, blockIdx.y, gsm);
}

// ===========================================================================
// Flash-attention v4 (unchanged from R12 — WIN; protect it)
// ===========================================================================
__global__ __launch_bounds__(128) void flash4()
{
    extern __shared__ float sm[];
    float* Qs = sm;                    // [128][68] pre-scaled
    float* Kt = sm + 128 * 68;         // [d][t] 64x68
    float* Vs = Kt + 64 * 68;          // [t][d] 64x68
    float* Ps = Vs + 64 * 68;          // [128][68]

    const int tid = threadIdx.x;
    const int bh  = blockIdx.y;
    const int r0  = blockIdx.x * 128;
    const int tx = tid & 7;
    const int ty = tid >> 3;
    const int ro = ty * 8;
    const float NEG_INF = __int_as_float(0xff800000u);

    const float* Qg = g_q + (size_t)bh * (LSEQ * HDIM);
    const float* Kg = g_k + (size_t)bh * (LSEQ * HDIM);
    const float* Vg = g_v + (size_t)bh * (LSEQ * HDIM);

#pragma unroll
    for (int i = 0; i < 16; i++) {
        int idx = tid + i * 128;
        int r = idx >> 4;
        int d4 = (idx & 15) << 2;
        float4 q = *(const float4*)(Qg + (size_t)(r0 + r) * HDIM + d4);
        *(float4*)&Qs[r * 68 + d4] =
            make_float4(q.x * 0.125f, q.y * 0.125f, q.z * 0.125f, q.w * 0.125f);
    }

    float mreg[8], sreg[8];
    u64 acc2[8][4];
#pragma unroll
    for (int i = 0; i < 8; i++) {
        mreg[i] = NEG_INF; sreg[i] = 0.f;
#pragma unroll
        for (int j = 0; j < 4; j++) acc2[i][j] = 0ull;
    }

    for (int t0 = 0; t0 < LSEQ; t0 += 64) {
        __syncthreads();
#pragma unroll
        for (int i = 0; i < 8; i++) {
            int idx = tid + i * 128;
            int t = idx >> 4;
            int d4 = (idx & 15) << 2;
            float4 kv = *(const float4*)(Kg + (size_t)(t0 + t) * HDIM + d4);
            Kt[(d4 + 0) * 68 + t] = kv.x;
            Kt[(d4 + 1) * 68 + t] = kv.y;
            Kt[(d4 + 2) * 68 + t] = kv.z;
            Kt[(d4 + 3) * 68 + t] = kv.w;
            *(float4*)&Vs[t * 68 + d4] = *(const float4*)(Vg + (size_t)(t0 + t) * HDIM + d4);
        }
        __syncthreads();

        u64 sacc2[8][4];
#pragma unroll
        for (int i = 0; i < 8; i++)
#pragma unroll
            for (int j = 0; j < 4; j++) sacc2[i][j] = 0ull;

#pragma unroll
        for (int d = 0; d < 64; d += 4) {
            u64 kp[4][4];
#pragma unroll
            for (int jj = 0; jj < 4; jj++) {
                float4 k0 = *(const float4*)&Kt[(d + jj) * 68 + tx * 4];
                float4 k1 = *(const float4*)&Kt[(d + jj) * 68 + 32 + tx * 4];
                kp[jj][0] = pk2(k0.x, k0.y); kp[jj][1] = pk2(k0.z, k0.w);
                kp[jj][2] = pk2(k1.x, k1.y); kp[jj][3] = pk2(k1.z, k1.w);
            }
#pragma unroll
            for (int i = 0; i < 8; i++) {
                float4 q = *(const float4*)&Qs[(ro + i) * 68 + d];
                u64 ap;
                ap = pk2(q.x, q.x);
                fma2(sacc2[i][0], ap, kp[0][0]); fma2(sacc2[i][1], ap, kp[0][1]);
                fma2(sacc2[i][2], ap, kp[0][2]); fma2(sacc2[i][3], ap, kp[0][3]);
                ap = pk2(q.y, q.y);
                fma2(sacc2[i][0], ap, kp[1][0]); fma2(sacc2[i][1], ap, kp[1][1]);
                fma2(sacc2[i][2], ap, kp[1][2]); fma2(sacc2[i][3], ap, kp[1][3]);
                ap = pk2(q.z, q.z);
                fma2(sacc2[i][0], ap, kp[2][0]); fma2(sacc2[i][1], ap, kp[2][1]);
                fma2(sacc2[i][2], ap, kp[2][2]); fma2(sacc2[i][3], ap, kp[2][3]);
                ap = pk2(q.w, q.w);
                fma2(sacc2[i][0], ap, kp[3][0]); fma2(sacc2[i][1], ap, kp[3][1]);
                fma2(sacc2[i][2], ap, kp[3][2]); fma2(sacc2[i][3], ap, kp[3][3]);
            }
        }

#pragma unroll
        for (int i = 0; i < 8; i++) {
            float f[8];
            upk2(sacc2[i][0], f[0], f[1]);
            upk2(sacc2[i][1], f[2], f[3]);
            upk2(sacc2[i][2], f[4], f[5]);
            upk2(sacc2[i][3], f[6], f[7]);
            float rmax = f[0];
#pragma unroll
            for (int j = 1; j < 8; j++) rmax = fmaxf(rmax, f[j]);
            rmax = fmaxf(rmax, __shfl_xor_sync(0xffffffffu, rmax, 1));
            rmax = fmaxf(rmax, __shfl_xor_sync(0xffffffffu, rmax, 2));
            rmax = fmaxf(rmax, __shfl_xor_sync(0xffffffffu, rmax, 4));
            float mn = fmaxf(mreg[i], rmax);
            float cc = __expf(mreg[i] - mn);
            mreg[i] = mn;
            float sum = 0.f;
#pragma unroll
            for (int j = 0; j < 8; j++) {
                f[j] = __expf(f[j] - mn);
                sum += f[j];
            }
            sum += __shfl_xor_sync(0xffffffffu, sum, 1);
            sum += __shfl_xor_sync(0xffffffffu, sum, 2);
            sum += __shfl_xor_sync(0xffffffffu, sum, 4);
            sreg[i] = sreg[i] * cc + sum;
            *(float4*)&Ps[(ro + i) * 68 + tx * 4] = make_float4(f[0], f[1], f[2], f[3]);
            *(float4*)&Ps[(ro + i) * 68 + 32 + tx * 4] = make_float4(f[4], f[5], f[6], f[7]);
            u64 cp = pk2(cc, cc);
#pragma unroll
            for (int j = 0; j < 4; j++) mul2(acc2[i][j], acc2[i][j], cp);
        }
        __syncwarp();

#pragma unroll
        for (int t = 0; t < 64; t += 4) {
            u64 vp[4][4];
#pragma unroll
            for (int jj = 0; jj < 4; jj++) {
                float4 v0 = *(const float4*)&Vs[(t + jj) * 68 + tx * 4];
                float4 v1 = *(const float4*)&Vs[(t + jj) * 68 + 32 + tx * 4];
                vp[jj][0] = pk2(v0.x, v0.y); vp[jj][1] = pk2(v0.z, v0.w);
                vp[jj][2] = pk2(v1.x, v1.y); vp[jj][3] = pk2(v1.z, v1.w);
            }
#pragma unroll
            for (int i = 0; i < 8; i++) {
                float4 p = *(const float4*)&Ps[(ro + i) * 68 + t];
                u64 ap;
                ap = pk2(p.x, p.x);
                fma2(acc2[i][0], ap, vp[0][0]); fma2(acc2[i][1], ap, vp[0][1]);
                fma2(acc2[i][2], ap, vp[0][2]); fma2(acc2[i][3], ap, vp[0][3]);
                ap = pk2(p.y, p.y);
                fma2(acc2[i][0], ap, vp[1][0]); fma2(acc2[i][1], ap, vp[1][1]);
                fma2(acc2[i][2], ap, vp[1][2]); fma2(acc2[i][3], ap, vp[1][3]);
                ap = pk2(p.z, p.z);
                fma2(acc2[i][0], ap, vp[2][0]); fma2(acc2[i][1], ap, vp[2][1]);
                fma2(acc2[i][2], ap, vp[2][2]); fma2(acc2[i][3], ap, vp[2][3]);
                ap = pk2(p.w, p.w);
                fma2(acc2[i][0], ap, vp[3][0]); fma2(acc2[i][1], ap, vp[3][1]);
                fma2(acc2[i][2], ap, vp[3][2]); fma2(acc2[i][3], ap, vp[3][3]);
            }
        }
    }

    float* Og = g_o + (size_t)bh * (LSEQ * HDIM);
#pragma unroll
    for (int i = 0; i < 8; i++) {
        float inv = 1.0f / sreg[i];
        float f0, f1, f2, f3, f4, f5, f6, f7;
        upk2(acc2[i][0], f0, f1);
        upk2(acc2[i][1], f2, f3);
        upk2(acc2[i][2], f4, f5);
        upk2(acc2[i][3], f6, f7);
        *(float4*)(Og + (size_t)(r0 + ro + i) * HDIM + tx * 4) =
            make_float4(f0 * inv, f1 * inv, f2 * inv, f3 * inv);
        *(float4*)(Og + (size_t)(r0 + ro + i) * HDIM + 32 + tx * 4) =
            make_float4(f4 * inv, f5 * inv, f6 * inv, f7 * inv);
    }
    if (tx == 0) {
#pragma unroll
        for (int i = 0; i < 8; i++) {
            g_m[(size_t)bh * LSEQ + r0 + ro + i] = mreg[i];
            g_s[(size_t)bh * LSEQ + r0 + ro + i] = sreg[i];
        }
    }
}

// ---------------------------------------------------------------------------
// Attention-matrix writer (only when out_size includes attention)
// ---------------------------------------------------------------------------
__global__ __launch_bounds__(256) void attnout_kernel(float* __restrict__ att)
{
    __shared__ float Qs[SQS];
    __shared__ float Kt[SQS];
    __shared__ float mrow[64];
    __shared__ float sinv[64];

    const int tid = threadIdx.x;
    const int bh  = blockIdx.y;
    const int r0  = blockIdx.x * 64;

    const float* Qg = g_q + (size_t)bh * (LSEQ * HDIM);
    const float* Kg = g_k + (size_t)bh * (LSEQ * HDIM);

#pragma unroll
    for (int i = 0; i < 4; i++) {
        int idx = tid + i * 256;
        int r = idx >> 4;
        int d4 = (idx & 15) << 2;
        float4 q = *(const float4*)(Qg + (size_t)(r0 + r) * HDIM + d4);
        *(float4*)&Qs[r * 68 + d4] =
            make_float4(q.x * 0.125f, q.y * 0.125f, q.z * 0.125f, q.w * 0.125f);
    }
    if (tid < 64) {
        mrow[tid] = g_m[(size_t)bh * LSEQ + r0 + tid];
        sinv[tid] = 1.0f / g_s[(size_t)bh * LSEQ + r0 + tid];
    }

    const int ro = (tid >> 4) * 4;
    const int co = (tid & 15) * 4;

    for (int t0 = 0; t0 < LSEQ; t0 += 64) {
        __syncthreads();
#pragma unroll
        for (int i = 0; i < 4; i++) {
            int idx = tid + i * 256;
            int t = idx >> 4;
            int d4 = (idx & 15) << 2;
            float4 kv = *(const float4*)(Kg + (size_t)(t0 + t) * HDIM + d4);
            Kt[(d4 + 0) * 68 + t] = kv.x;
            Kt[(d4 + 1) * 68 + t] = kv.y;
            Kt[(d4 + 2) * 68 + t] = kv.z;
            Kt[(d4 + 3) * 68 + t] = kv.w;
        }
        __syncthreads();

        float sacc[4][4];
#pragma unroll
        for (int i = 0; i < 4; i++)
#pragma unroll
            for (int j = 0; j < 4; j++) sacc[i][j] = 0.f;
#pragma unroll
        for (int d = 0; d < 64; d += 4) {
            float4 q4[4], kv[4];
#pragma unroll
            for (int i = 0; i < 4; i++) q4[i] = *(const float4*)&Qs[(ro + i) * 68 + d];
#pragma unroll
            for (int jj = 0; jj < 4; jj++) kv[jj] = *(const float4*)&Kt[(d + jj) * 68 + co];
#pragma unroll
            for (int i = 0; i < 4; i++) {
                float qa[4] = {q4[i].x, q4[i].y, q4[i].z, q4[i].w};
#pragma unroll
                for (int jj = 0; jj < 4; jj++) {
                    sacc[i][0] += qa[jj] * kv[jj].x;
                    sacc[i][1] += qa[jj] * kv[jj].y;
                    sacc[i][2] += qa[jj] * kv[jj].z;
                    sacc[i][3] += qa[jj] * kv[jj].w;
                }
            }
        }
#pragma unroll
        for (int i = 0; i < 4; i++) {
            float mi = mrow[ro + i];
            float si = sinv[ro + i];
            float4 o = make_float4(__expf(sacc[i][0] - mi) * si,
                                   __expf(sacc[i][1] - mi) * si,
                                   __expf(sacc[i][2] - mi) * si,
                                   __expf(sacc[i][3] - mi) * si);
            *(float4*)(att + ((size_t)bh * LSEQ + r0 + ro + i) * LSEQ + t0 + co) = o;
        }
    }
}

// ---------------------------------------------------------------------------
extern "C" void kernel_launch(void* const* d_in, const int* in_sizes, int n_in,
                              void* d_out, int out_size)
{
    const float* query = (const float*)d_in[0];
    const float* key   = (const float*)d_in[1];
    const float* value = (const float*)d_in[2];
    const float* Wq    = (const float*)d_in[3];
    const float* Wk    = (const float*)d_in[4];
    const float* Wv    = (const float*)d_in[5];
    const float* Wo    = (const float*)d_in[6];
    const float* bo    = (const float*)d_in[7];
    float* out = (float*)d_out;

    float *qp, *kp, *vp, *op;
    cudaGetSymbolAddress((void**)&qp, g_q);
    cudaGetSymbolAddress((void**)&kp, g_k);
    cudaGetSymbolAddress((void**)&vp, g_v);
    cudaGetSymbolAddress((void**)&op, g_o);

    cudaFuncSetAttribute(gemm_qkv, cudaFuncAttributeMaxDynamicSharedMemorySize, G_SMEM_B);
    cudaFuncSetAttribute(gemm_out, cudaFuncAttributeMaxDynamicSharedMemorySize, G_SMEM_B);

    // Fused Q/K/V projections: one launch, z selects the GEMM.
    gemm_qkv<<<dim3(DMODEL / 128, M_TOT / 128, 3), 128, G_SMEM_B>>>(
        query, key, value, Wq, Wk, Wv, qp, kp, vp);

    cudaFuncSetAttribute(flash4, cudaFuncAttributeMaxDynamicSharedMemorySize, FSHM);
    flash4<<<dim3(LSEQ / 128, NB * NH), 128, FSHM>>>();

    gemm_out<<<dim3(DMODEL / 128, M_TOT / 128), 128, G_SMEM_B>>>(op, Wo, bo, out);

    if (out_size > OUT_ELEMS) {
        attnout_kernel<<<dim3(LSEQ / 64, NB * NH), 256>>>(out + OUT_ELEMS);
    }
}

// round 15
// speedup vs baseline: 1.7130x; 1.7130x over previous
#include <cuda_runtime.h>
#include <cstdint>

#define NB 4
#define NH 16
#define LSEQ 2048
#define HDIM 64
#define DMODEL 1024
#define M_TOT (NB*LSEQ)            // 8192
#define OUT_ELEMS (M_TOT*DMODEL)   // 8388608

// GEMM v4 tiling: BM=128, BN=128, BK=32, 128 threads, 8x16/thread, double-buffered
#define GBK 32
#define GNCHUNK (DMODEL/GBK)       // 32
#define G_TILE_F (GBK*132)         // floats per (A or B) buffer: 4224
#define G_SMEM_B (4*G_TILE_F*4)    // 2 bufs x (A+B) = 67584 bytes

// flash4: Q-block 128 rows, 128 threads, 8x8/thread
#define FSHM ((128+64+64+128)*68*4)   // Qs,Kt,Vs,Ps = 104448 bytes
// attnout5: Qs[128][68] + Kt[64][68] + mrow[128] + sinv[128]
#define ASHM ((128+64)*68*4 + 256*4)  // 53248 bytes

typedef unsigned long long u64;

// ---- packed fp32x2 helpers ----
__device__ __forceinline__ u64 pk2(float lo, float hi) {
    u64 r; asm("mov.b64 %0, {%1, %2};" : "=l"(r) : "f"(lo), "f"(hi)); return r;
}
__device__ __forceinline__ void upk2(u64 v, float& lo, float& hi) {
    asm("mov.b64 {%0, %1}, %2;" : "=f"(lo), "=f"(hi) : "l"(v));
}
__device__ __forceinline__ void fma2(u64& d, u64 a, u64 b) {
    asm("fma.rn.f32x2 %0, %1, %2, %3;" : "=l"(d) : "l"(a), "l"(b), "l"(d));
}
__device__ __forceinline__ void mul2(u64& d, u64 a, u64 b) {
    asm("mul.rn.f32x2 %0, %1, %2;" : "=l"(d) : "l"(a), "l"(b));
}

// Scratch (device globals; no allocation allowed)
__device__ float g_q[NB*NH*LSEQ*HDIM];
__device__ float g_k[NB*NH*LSEQ*HDIM];
__device__ float g_v[NB*NH*LSEQ*HDIM];
__device__ float g_o[NB*NH*LSEQ*HDIM];
__device__ float g_m[NB*NH*LSEQ];
__device__ float g_s[NB*NH*LSEQ];

// ===========================================================================
// GEMM v4 (packed f32x2, 0.75 B/MAC) — exact R12 winner.
// ===========================================================================
__global__ __launch_bounds__(128) void gemm4(
    const float* __restrict__ A, const float* __restrict__ W,
    const float* __restrict__ bias, float* __restrict__ C,
    int gatherA, int scatterC)
{
    extern __shared__ float gsm[];
    const int tid = threadIdx.x;
    const int tx = tid & 7;          // col group: cols tx*4 + g*32
    const int ty = tid >> 3;         // row group: rows ty*8..+7
    const int m0 = blockIdx.y * 128;
    const int n0 = blockIdx.x * 128;

    u64 acc2[8][8];
#pragma unroll
    for (int i = 0; i < 8; i++)
#pragma unroll
        for (int j = 0; j < 8; j++) acc2[i][j] = 0ull;

    float4 ra[8], rb[8];
#pragma unroll
    for (int ii = 0; ii < 8; ii++) {
        int idx = tid + ii * 128;
        int r = idx >> 3;
        int c4 = (idx & 7) << 2;
        if (!gatherA) {
            ra[ii] = *(const float4*)(A + (size_t)(m0 + r) * DMODEL + c4);
        } else {
            int m = m0 + r, k = c4;
            ra[ii] = *(const float4*)(A +
                (((size_t)((m >> 11) * NH + (k >> 6)) * LSEQ + (m & 2047)) * HDIM) + (k & 63));
        }
        rb[ii] = *(const float4*)(W + (size_t)(n0 + r) * DMODEL + c4);
    }

    for (int c = 0; c < GNCHUNK; c++) {
        const int buf = c & 1;
        float* As = gsm + buf * G_TILE_F;
        float* Bs = gsm + 2 * G_TILE_F + buf * G_TILE_F;

#pragma unroll
        for (int ii = 0; ii < 8; ii++) {
            int idx = tid + ii * 128;
            int r = idx >> 3;
            int c4 = (idx & 7) << 2;
            As[(c4 + 0) * 132 + r] = ra[ii].x;
            As[(c4 + 1) * 132 + r] = ra[ii].y;
            As[(c4 + 2) * 132 + r] = ra[ii].z;
            As[(c4 + 3) * 132 + r] = ra[ii].w;
            Bs[(c4 + 0) * 132 + r] = rb[ii].x;
            Bs[(c4 + 1) * 132 + r] = rb[ii].y;
            Bs[(c4 + 2) * 132 + r] = rb[ii].z;
            Bs[(c4 + 3) * 132 + r] = rb[ii].w;
        }
        __syncthreads();

        if (c + 1 < GNCHUNK) {
            int k0 = (c + 1) * GBK;
#pragma unroll
            for (int ii = 0; ii < 8; ii++) {
                int idx = tid + ii * 128;
                int r = idx >> 3;
                int c4 = (idx & 7) << 2;
                if (!gatherA) {
                    ra[ii] = *(const float4*)(A + (size_t)(m0 + r) * DMODEL + k0 + c4);
                } else {
                    int m = m0 + r, k = k0 + c4;
                    ra[ii] = *(const float4*)(A +
                        (((size_t)((m >> 11) * NH + (k >> 6)) * LSEQ + (m & 2047)) * HDIM) + (k & 63));
                }
                rb[ii] = *(const float4*)(W + (size_t)(n0 + r) * DMODEL + k0 + c4);
            }
        }

#pragma unroll
        for (int k = 0; k < GBK; k++) {
            float4 a0 = *(const float4*)&As[k * 132 + ty * 8];
            float4 a1 = *(const float4*)&As[k * 132 + ty * 8 + 4];
            u64 bp[8];
#pragma unroll
            for (int gq = 0; gq < 4; gq++) {
                float4 b = *(const float4*)&Bs[k * 132 + tx * 4 + gq * 32];
                bp[gq * 2 + 0] = pk2(b.x, b.y);
                bp[gq * 2 + 1] = pk2(b.z, b.w);
            }
            float av[8] = {a0.x, a0.y, a0.z, a0.w, a1.x, a1.y, a1.z, a1.w};
#pragma unroll
            for (int i = 0; i < 8; i++) {
                u64 ap = pk2(av[i], av[i]);
#pragma unroll
                for (int j = 0; j < 8; j++) fma2(acc2[i][j], ap, bp[j]);
            }
        }
        __syncthreads();
    }

#pragma unroll
    for (int i = 0; i < 8; i++) {
        int m = m0 + ty * 8 + i;
#pragma unroll
        for (int gq = 0; gq < 4; gq++) {
            int n = n0 + tx * 4 + gq * 32;
            float f0, f1, f2, f3;
            upk2(acc2[i][gq * 2 + 0], f0, f1);
            upk2(acc2[i][gq * 2 + 1], f2, f3);
            if (bias) {
                float4 bv = *(const float4*)(bias + n);
                f0 += bv.x; f1 += bv.y; f2 += bv.z; f3 += bv.w;
            }
            float4 o = make_float4(f0, f1, f2, f3);
            float* dst;
            if (scatterC) {
                dst = C + (((size_t)((m >> 11) * NH + (n >> 6)) * LSEQ + (m & 2047)) * HDIM)
                        + (n & 63);
            } else {
                dst = C + (size_t)m * DMODEL + n;
            }
            *(float4*)dst = o;
        }
    }
}

// ===========================================================================
// Flash-attention v4 — exact R12 winner.
// ===========================================================================
__global__ __launch_bounds__(128) void flash4()
{
    extern __shared__ float sm[];
    float* Qs = sm;                    // [128][68] pre-scaled
    float* Kt = sm + 128 * 68;         // [d][t] 64x68
    float* Vs = Kt + 64 * 68;          // [t][d] 64x68
    float* Ps = Vs + 64 * 68;          // [128][68]

    const int tid = threadIdx.x;
    const int bh  = blockIdx.y;
    const int r0  = blockIdx.x * 128;
    const int tx = tid & 7;
    const int ty = tid >> 3;
    const int ro = ty * 8;
    const float NEG_INF = __int_as_float(0xff800000u);

    const float* Qg = g_q + (size_t)bh * (LSEQ * HDIM);
    const float* Kg = g_k + (size_t)bh * (LSEQ * HDIM);
    const float* Vg = g_v + (size_t)bh * (LSEQ * HDIM);

#pragma unroll
    for (int i = 0; i < 16; i++) {
        int idx = tid + i * 128;
        int r = idx >> 4;
        int d4 = (idx & 15) << 2;
        float4 q = *(const float4*)(Qg + (size_t)(r0 + r) * HDIM + d4);
        *(float4*)&Qs[r * 68 + d4] =
            make_float4(q.x * 0.125f, q.y * 0.125f, q.z * 0.125f, q.w * 0.125f);
    }

    float mreg[8], sreg[8];
    u64 acc2[8][4];
#pragma unroll
    for (int i = 0; i < 8; i++) {
        mreg[i] = NEG_INF; sreg[i] = 0.f;
#pragma unroll
        for (int j = 0; j < 4; j++) acc2[i][j] = 0ull;
    }

    for (int t0 = 0; t0 < LSEQ; t0 += 64) {
        __syncthreads();
#pragma unroll
        for (int i = 0; i < 8; i++) {
            int idx = tid + i * 128;
            int t = idx >> 4;
            int d4 = (idx & 15) << 2;
            float4 kv = *(const float4*)(Kg + (size_t)(t0 + t) * HDIM + d4);
            Kt[(d4 + 0) * 68 + t] = kv.x;
            Kt[(d4 + 1) * 68 + t] = kv.y;
            Kt[(d4 + 2) * 68 + t] = kv.z;
            Kt[(d4 + 3) * 68 + t] = kv.w;
            *(float4*)&Vs[t * 68 + d4] = *(const float4*)(Vg + (size_t)(t0 + t) * HDIM + d4);
        }
        __syncthreads();

        u64 sacc2[8][4];
#pragma unroll
        for (int i = 0; i < 8; i++)
#pragma unroll
            for (int j = 0; j < 4; j++) sacc2[i][j] = 0ull;

#pragma unroll
        for (int d = 0; d < 64; d += 4) {
            u64 kp[4][4];
#pragma unroll
            for (int jj = 0; jj < 4; jj++) {
                float4 k0 = *(const float4*)&Kt[(d + jj) * 68 + tx * 4];
                float4 k1 = *(const float4*)&Kt[(d + jj) * 68 + 32 + tx * 4];
                kp[jj][0] = pk2(k0.x, k0.y); kp[jj][1] = pk2(k0.z, k0.w);
                kp[jj][2] = pk2(k1.x, k1.y); kp[jj][3] = pk2(k1.z, k1.w);
            }
#pragma unroll
            for (int i = 0; i < 8; i++) {
                float4 q = *(const float4*)&Qs[(ro + i) * 68 + d];
                u64 ap;
                ap = pk2(q.x, q.x);
                fma2(sacc2[i][0], ap, kp[0][0]); fma2(sacc2[i][1], ap, kp[0][1]);
                fma2(sacc2[i][2], ap, kp[0][2]); fma2(sacc2[i][3], ap, kp[0][3]);
                ap = pk2(q.y, q.y);
                fma2(sacc2[i][0], ap, kp[1][0]); fma2(sacc2[i][1], ap, kp[1][1]);
                fma2(sacc2[i][2], ap, kp[1][2]); fma2(sacc2[i][3], ap, kp[1][3]);
                ap = pk2(q.z, q.z);
                fma2(sacc2[i][0], ap, kp[2][0]); fma2(sacc2[i][1], ap, kp[2][1]);
                fma2(sacc2[i][2], ap, kp[2][2]); fma2(sacc2[i][3], ap, kp[2][3]);
                ap = pk2(q.w, q.w);
                fma2(sacc2[i][0], ap, kp[3][0]); fma2(sacc2[i][1], ap, kp[3][1]);
                fma2(sacc2[i][2], ap, kp[3][2]); fma2(sacc2[i][3], ap, kp[3][3]);
            }
        }

#pragma unroll
        for (int i = 0; i < 8; i++) {
            float f[8];
            upk2(sacc2[i][0], f[0], f[1]);
            upk2(sacc2[i][1], f[2], f[3]);
            upk2(sacc2[i][2], f[4], f[5]);
            upk2(sacc2[i][3], f[6], f[7]);
            float rmax = f[0];
#pragma unroll
            for (int j = 1; j < 8; j++) rmax = fmaxf(rmax, f[j]);
            rmax = fmaxf(rmax, __shfl_xor_sync(0xffffffffu, rmax, 1));
            rmax = fmaxf(rmax, __shfl_xor_sync(0xffffffffu, rmax, 2));
            rmax = fmaxf(rmax, __shfl_xor_sync(0xffffffffu, rmax, 4));
            float mn = fmaxf(mreg[i], rmax);
            float cc = __expf(mreg[i] - mn);
            mreg[i] = mn;
            float sum = 0.f;
#pragma unroll
            for (int j = 0; j < 8; j++) {
                f[j] = __expf(f[j] - mn);
                sum += f[j];
            }
            sum += __shfl_xor_sync(0xffffffffu, sum, 1);
            sum += __shfl_xor_sync(0xffffffffu, sum, 2);
            sum += __shfl_xor_sync(0xffffffffu, sum, 4);
            sreg[i] = sreg[i] * cc + sum;
            *(float4*)&Ps[(ro + i) * 68 + tx * 4] = make_float4(f[0], f[1], f[2], f[3]);
            *(float4*)&Ps[(ro + i) * 68 + 32 + tx * 4] = make_float4(f[4], f[5], f[6], f[7]);
            u64 cp = pk2(cc, cc);
#pragma unroll
            for (int j = 0; j < 4; j++) mul2(acc2[i][j], acc2[i][j], cp);
        }
        __syncwarp();

#pragma unroll
        for (int t = 0; t < 64; t += 4) {
            u64 vp[4][4];
#pragma unroll
            for (int jj = 0; jj < 4; jj++) {
                float4 v0 = *(const float4*)&Vs[(t + jj) * 68 + tx * 4];
                float4 v1 = *(const float4*)&Vs[(t + jj) * 68 + 32 + tx * 4];
                vp[jj][0] = pk2(v0.x, v0.y); vp[jj][1] = pk2(v0.z, v0.w);
                vp[jj][2] = pk2(v1.x, v1.y); vp[jj][3] = pk2(v1.z, v1.w);
            }
#pragma unroll
            for (int i = 0; i < 8; i++) {
                float4 p = *(const float4*)&Ps[(ro + i) * 68 + t];
                u64 ap;
                ap = pk2(p.x, p.x);
                fma2(acc2[i][0], ap, vp[0][0]); fma2(acc2[i][1], ap, vp[0][1]);
                fma2(acc2[i][2], ap, vp[0][2]); fma2(acc2[i][3], ap, vp[0][3]);
                ap = pk2(p.y, p.y);
                fma2(acc2[i][0], ap, vp[1][0]); fma2(acc2[i][1], ap, vp[1][1]);
                fma2(acc2[i][2], ap, vp[1][2]); fma2(acc2[i][3], ap, vp[1][3]);
                ap = pk2(p.z, p.z);
                fma2(acc2[i][0], ap, vp[2][0]); fma2(acc2[i][1], ap, vp[2][1]);
                fma2(acc2[i][2], ap, vp[2][2]); fma2(acc2[i][3], ap, vp[2][3]);
                ap = pk2(p.w, p.w);
                fma2(acc2[i][0], ap, vp[3][0]); fma2(acc2[i][1], ap, vp[3][1]);
                fma2(acc2[i][2], ap, vp[3][2]); fma2(acc2[i][3], ap, vp[3][3]);
            }
        }
    }

    float* Og = g_o + (size_t)bh * (LSEQ * HDIM);
#pragma unroll
    for (int i = 0; i < 8; i++) {
        float inv = 1.0f / sreg[i];
        float f0, f1, f2, f3, f4, f5, f6, f7;
        upk2(acc2[i][0], f0, f1);
        upk2(acc2[i][1], f2, f3);
        upk2(acc2[i][2], f4, f5);
        upk2(acc2[i][3], f6, f7);
        *(float4*)(Og + (size_t)(r0 + ro + i) * HDIM + tx * 4) =
            make_float4(f0 * inv, f1 * inv, f2 * inv, f3 * inv);
        *(float4*)(Og + (size_t)(r0 + ro + i) * HDIM + 32 + tx * 4) =
            make_float4(f4 * inv, f5 * inv, f6 * inv, f7 * inv);
    }
    if (tx == 0) {
#pragma unroll
        for (int i = 0; i < 8; i++) {
            g_m[(size_t)bh * LSEQ + r0 + ro + i] = mreg[i];
            g_s[(size_t)bh * LSEQ + r0 + ro + i] = sreg[i];
        }
    }
}

// ===========================================================================
// attnout5: attention-matrix writer in the flash4 idiom (8x8/thread, f32x2).
// Recomputes S for a 128-row Q block, applies stored (m, s), stores float4s.
// ===========================================================================
__global__ __launch_bounds__(128) void attnout5(float* __restrict__ att)
{
    extern __shared__ float sm[];
    float* Qs   = sm;                  // [128][68] pre-scaled
    float* Kt   = sm + 128 * 68;       // [d][t] 64x68
    float* mrow = Kt + 64 * 68;        // [128]
    float* sinv = mrow + 128;          // [128]

    const int tid = threadIdx.x;
    const int bh  = blockIdx.y;
    const int r0  = blockIdx.x * 128;
    const int tx = tid & 7;
    const int ty = tid >> 3;
    const int ro = ty * 8;

    const float* Qg = g_q + (size_t)bh * (LSEQ * HDIM);
    const float* Kg = g_k + (size_t)bh * (LSEQ * HDIM);

#pragma unroll
    for (int i = 0; i < 16; i++) {
        int idx = tid + i * 128;
        int r = idx >> 4;
        int d4 = (idx & 15) << 2;
        float4 q = *(const float4*)(Qg + (size_t)(r0 + r) * HDIM + d4);
        *(float4*)&Qs[r * 68 + d4] =
            make_float4(q.x * 0.125f, q.y * 0.125f, q.z * 0.125f, q.w * 0.125f);
    }
    if (tid < 128) {
        mrow[tid] = g_m[(size_t)bh * LSEQ + r0 + tid];
        sinv[tid] = 1.0f / g_s[(size_t)bh * LSEQ + r0 + tid];
    }

    float mr[8], sv[8];

    for (int t0 = 0; t0 < LSEQ; t0 += 64) {
        __syncthreads();   // prior-iter Kt reads done (also covers Q/m/s init)
#pragma unroll
        for (int i = 0; i < 8; i++) {
            int idx = tid + i * 128;
            int t = idx >> 4;
            int d4 = (idx & 15) << 2;
            float4 kv = *(const float4*)(Kg + (size_t)(t0 + t) * HDIM + d4);
            Kt[(d4 + 0) * 68 + t] = kv.x;
            Kt[(d4 + 1) * 68 + t] = kv.y;
            Kt[(d4 + 2) * 68 + t] = kv.z;
            Kt[(d4 + 3) * 68 + t] = kv.w;
        }
        __syncthreads();

        if (t0 == 0) {
#pragma unroll
            for (int i = 0; i < 8; i++) {
                mr[i] = mrow[ro + i];
                sv[i] = sinv[ro + i];
            }
        }

        u64 sacc2[8][4];
#pragma unroll
        for (int i = 0; i < 8; i++)
#pragma unroll
            for (int j = 0; j < 4; j++) sacc2[i][j] = 0ull;

#pragma unroll
        for (int d = 0; d < 64; d += 4) {
            u64 kp[4][4];
#pragma unroll
            for (int jj = 0; jj < 4; jj++) {
                float4 k0 = *(const float4*)&Kt[(d + jj) * 68 + tx * 4];
                float4 k1 = *(const float4*)&Kt[(d + jj) * 68 + 32 + tx * 4];
                kp[jj][0] = pk2(k0.x, k0.y); kp[jj][1] = pk2(k0.z, k0.w);
                kp[jj][2] = pk2(k1.x, k1.y); kp[jj][3] = pk2(k1.z, k1.w);
            }
#pragma unroll
            for (int i = 0; i < 8; i++) {
                float4 q = *(const float4*)&Qs[(ro + i) * 68 + d];
                u64 ap;
                ap = pk2(q.x, q.x);
                fma2(sacc2[i][0], ap, kp[0][0]); fma2(sacc2[i][1], ap, kp[0][1]);
                fma2(sacc2[i][2], ap, kp[0][2]); fma2(sacc2[i][3], ap, kp[0][3]);
                ap = pk2(q.y, q.y);
                fma2(sacc2[i][0], ap, kp[1][0]); fma2(sacc2[i][1], ap, kp[1][1]);
                fma2(sacc2[i][2], ap, kp[1][2]); fma2(sacc2[i][3], ap, kp[1][3]);
                ap = pk2(q.z, q.z);
                fma2(sacc2[i][0], ap, kp[2][0]); fma2(sacc2[i][1], ap, kp[2][1]);
                fma2(sacc2[i][2], ap, kp[2][2]); fma2(sacc2[i][3], ap, kp[2][3]);
                ap = pk2(q.w, q.w);
                fma2(sacc2[i][0], ap, kp[3][0]); fma2(sacc2[i][1], ap, kp[3][1]);
                fma2(sacc2[i][2], ap, kp[3][2]); fma2(sacc2[i][3], ap, kp[3][3]);
            }
        }

#pragma unroll
        for (int i = 0; i < 8; i++) {
            float f[8];
            upk2(sacc2[i][0], f[0], f[1]);
            upk2(sacc2[i][1], f[2], f[3]);
            upk2(sacc2[i][2], f[4], f[5]);
            upk2(sacc2[i][3], f[6], f[7]);
            float* dst = att + ((size_t)bh * LSEQ + r0 + ro + i) * LSEQ + t0;
            *(float4*)(dst + tx * 4) =
                make_float4(__expf(f[0] - mr[i]) * sv[i], __expf(f[1] - mr[i]) * sv[i],
                            __expf(f[2] - mr[i]) * sv[i], __expf(f[3] - mr[i]) * sv[i]);
            *(float4*)(dst + 32 + tx * 4) =
                make_float4(__expf(f[4] - mr[i]) * sv[i], __expf(f[5] - mr[i]) * sv[i],
                            __expf(f[6] - mr[i]) * sv[i], __expf(f[7] - mr[i]) * sv[i]);
        }
    }
}

// ---------------------------------------------------------------------------
extern "C" void kernel_launch(void* const* d_in, const int* in_sizes, int n_in,
                              void* d_out, int out_size)
{
    const float* query = (const float*)d_in[0];
    const float* key   = (const float*)d_in[1];
    const float* value = (const float*)d_in[2];
    const float* Wq    = (const float*)d_in[3];
    const float* Wk    = (const float*)d_in[4];
    const float* Wv    = (const float*)d_in[5];
    const float* Wo    = (const float*)d_in[6];
    const float* bo    = (const float*)d_in[7];
    float* out = (float*)d_out;

    float *qp, *kp, *vp, *op;
    cudaGetSymbolAddress((void**)&qp, g_q);
    cudaGetSymbolAddress((void**)&kp, g_k);
    cudaGetSymbolAddress((void**)&vp, g_v);
    cudaGetSymbolAddress((void**)&op, g_o);

    cudaFuncSetAttribute(gemm4, cudaFuncAttributeMaxDynamicSharedMemorySize, G_SMEM_B);
    dim3 gg(DMODEL / 128, M_TOT / 128);  // (8, 64)
    gemm4<<<gg, 128, G_SMEM_B>>>(query, Wq, nullptr, qp, 0, 1);
    gemm4<<<gg, 128, G_SMEM_B>>>(key,   Wk, nullptr, kp, 0, 1);
    gemm4<<<gg, 128, G_SMEM_B>>>(value, Wv, nullptr, vp, 0, 1);

    cudaFuncSetAttribute(flash4, cudaFuncAttributeMaxDynamicSharedMemorySize, FSHM);
    flash4<<<dim3(LSEQ / 128, NB * NH), 128, FSHM>>>();

    gemm4<<<gg, 128, G_SMEM_B>>>(op, Wo, bo, out, 1, 0);

    if (out_size > OUT_ELEMS) {
        cudaFuncSetAttribute(attnout5, cudaFuncAttributeMaxDynamicSharedMemorySize, ASHM);
        attnout5<<<dim3(LSEQ / 128, NB * NH), 128, ASHM>>>(out + OUT_ELEMS);
    }
}